// round 11
// baseline (speedup 1.0000x reference)
#include <cuda_runtime.h>
#include <cuda_fp16.h>
#include <cstdint>

#define TT 16384
#define DD 2048
#define EE 64
#define BR 64                  // rows per CTA
#define NT 192                 // 4 consumer warps + 2 producer warps
#define NCH 64                 // K chunks of 32 (full K per CTA)
#define NRING 4

// ---- smem: B ring, 4 stages x 8KB (512 uint4 per stage) ----
#define STAGE_U4 512
#define RING_U4 (NRING * STAGE_U4)         // 2048 uint4 = 32KB
#define SMEM_BYTES 34048                   // ring 32768 + epilogue tail (see overlay)

// epilogue overlay (u32 offsets; board reuses ring space)
#define SC2 66
#define CNT (BR * SC2)                     // 4224
#define I1A (CNT + 64)
#define I2A (I1A + 64)
#define G1A (I2A + 64)
#define G2A (G1A + 64)                     // end 4480 u32 = 17920 B < 32KB ring

// ---- output layout (floats) ----
#define IDX_OFF  ((size_t)TT * EE)
#define GATE_OFF (IDX_OFF + 2 * (size_t)TT)
#define ACT_OFF  (GATE_OFF + 2 * (size_t)TT)
#define FULL_OUT (ACT_OFF + EE)

// w pre-split fp16 hi/lo, fragment-major: [k16-step 128][nb 8][lane 32] uint4
// uint4 = {b0_hi, b1_hi, b0_lo, b1_lo}
__device__ uint4 g_w_frag[128 * 8 * 32];

__device__ __forceinline__ uint32_t packh2(__half a, __half b) {
    uint32_t u;
    asm("mov.b32 %0, {%1, %2};" : "=r"(u) : "h"(__half_as_ushort(a)), "h"(__half_as_ushort(b)));
    return u;
}
__device__ __forceinline__ void split_f16(float x, __half& h, __half& l) {
    h = __float2half_rn(x);
    l = __float2half_rn(x - __half2float(h));
}
__device__ __forceinline__ uint32_t split2(float2 v, uint32_t& lo) {
    __half hx, lx, hy, ly;
    split_f16(v.x, hx, lx);
    split_f16(v.y, hy, ly);
    lo = packh2(lx, ly);
    return packh2(hx, hy);
}
__device__ __forceinline__ void mma_f16(float* d, const uint32_t* a, uint32_t b0, uint32_t b1) {
    asm volatile(
        "mma.sync.aligned.m16n8k16.row.col.f32.f16.f16.f32 "
        "{%0,%1,%2,%3}, {%4,%5,%6,%7}, {%8,%9}, {%0,%1,%2,%3};"
        : "+f"(d[0]), "+f"(d[1]), "+f"(d[2]), "+f"(d[3])
        : "r"(a[0]), "r"(a[1]), "r"(a[2]), "r"(a[3]), "r"(b0), "r"(b1));
}
#define BAR_ARRIVE(id) asm volatile("bar.arrive %0, %1;" :: "r"(id), "r"(NT))
#define BAR_SYNC(id)   asm volatile("bar.sync %0, %1;"   :: "r"(id), "r"(NT) : "memory")
#define FULL_B(b) (1 + (b))
#define FREE_B(b) (5 + (b))

// ======================= prep: w -> fragment-major fp16 hi/lo =======================
__global__ void prep_kernel(const float* __restrict__ w, float* __restrict__ out, int we) {
    int t = blockIdx.x * 256 + threadIdx.x;   // 65536 threads, one per u32 pair
    int q = t >> 1, b = t & 1;
    int ks = q >> 8, rem = q & 255, nb = rem >> 5, l = rem & 31;
    int n = nb * 8 + (l >> 2), tig = l & 3;
    int k0 = ks * 16 + 2 * tig + b * 8;
    float w0 = w[(size_t)k0 * EE + n];
    float w1 = w[(size_t)(k0 + 1) * EE + n];
    __half h0, l0, h1, l1;
    split_f16(w0, h0, l0);
    split_f16(w1, h1, l1);
    uint32_t* o32 = (uint32_t*)g_w_frag;
    o32[q * 4 + b]     = packh2(h0, h1);   // hi
    o32[q * 4 + 2 + b] = packh2(l0, l1);   // lo
    if (we && t < EE) out[ACT_OFF + t] = 0.0f;
}

// ======================= main: 256 CTAs x 64 rows, A-direct + B-ring =======================
__global__ __launch_bounds__(NT, 2)
void router_mma_kernel(const float* __restrict__ x,
                       const float* __restrict__ noise,
                       float* __restrict__ out,
                       int write_extras) {
    extern __shared__ uint32_t smu[];
    uint4* ring = (uint4*)smu;
    const int tid = threadIdx.x;
    const int wid = tid >> 5;
    const int lid = tid & 31;
    const int g   = lid >> 2;
    const int t4  = lid & 3;
    const int row0 = blockIdx.x * BR;
    const bool is_consumer = (wid < 4);

    float acc[8][4];
#pragma unroll
    for (int nb = 0; nb < 8; nb++)
#pragma unroll
        for (int i = 0; i < 4; i++) acc[nb][i] = 0.0f;

    if (!is_consumer) {
        // ================= PRODUCER: warps 4,5 stream B frags into the ring =================
        const int pw = wid - 4;            // 0 or 1
        for (int c = 0; c < NCH; ++c) {
            const int b = c & 3;
            // issue this chunk's 8 LDG.128 first (latency hidden behind FREE wait)
            uint4 br[8];
            const uint4* Bg = g_w_frag + (size_t)c * 512 + pw * 256 + lid;
#pragma unroll
            for (int j = 0; j < 8; j++) br[j] = Bg[j * 32];
            if (c >= NRING) BAR_SYNC(FREE_B(b));
            uint4* Bs = ring + b * STAGE_U4 + pw * 256 + lid;
#pragma unroll
            for (int j = 0; j < 8; j++) Bs[j * 32] = br[j];
            BAR_ARRIVE(FULL_B(b));
        }
    } else {
        // ================= CONSUMER: warps 0..3, 16 rows each, A direct from gmem =================
        // A fragment rows for this thread
        const float* xr0 = x + (size_t)(row0 + wid * 16 + g) * DD + 2 * t4;
        const float* xr8 = xr0 + 8 * (size_t)DD;

        // prefetch chunk 0 A
        float2 av[8], avn[8];
#pragma unroll
        for (int ks = 0; ks < 2; ks++) {
            av[ks * 4 + 0] = *(const float2*)(xr0 + ks * 16);
            av[ks * 4 + 1] = *(const float2*)(xr0 + ks * 16 + 8);
            av[ks * 4 + 2] = *(const float2*)(xr8 + ks * 16);
            av[ks * 4 + 3] = *(const float2*)(xr8 + ks * 16 + 8);
        }

        for (int c = 0; c < NCH; ++c) {
            const int b = c & 3;
            // prefetch next chunk's A (clamped harmless reload on last iter)
            const int cn = (c + 1 < NCH) ? c + 1 : c;
#pragma unroll
            for (int ks = 0; ks < 2; ks++) {
                avn[ks * 4 + 0] = *(const float2*)(xr0 + cn * 32 + ks * 16);
                avn[ks * 4 + 1] = *(const float2*)(xr0 + cn * 32 + ks * 16 + 8);
                avn[ks * 4 + 2] = *(const float2*)(xr8 + cn * 32 + ks * 16);
                avn[ks * 4 + 3] = *(const float2*)(xr8 + cn * 32 + ks * 16 + 8);
            }

            BAR_SYNC(FULL_B(b));
            const uint4* Bs = ring + b * STAGE_U4 + lid;
#pragma unroll
            for (int ks = 0; ks < 2; ks++) {
                uint4 bv[8];
#pragma unroll
                for (int nb = 0; nb < 8; nb++) bv[nb] = Bs[(ks * 8 + nb) * 32];

                uint32_t ah[4], al[4];
                ah[0] = split2(av[ks * 4 + 0], al[0]);
                ah[1] = split2(av[ks * 4 + 2], al[1]);
                ah[2] = split2(av[ks * 4 + 1], al[2]);
                ah[3] = split2(av[ks * 4 + 3], al[3]);

#pragma unroll
                for (int nb = 0; nb < 8; nb++) mma_f16(acc[nb], ah, bv[nb].x, bv[nb].y);  // h*h
#pragma unroll
                for (int nb = 0; nb < 8; nb++) mma_f16(acc[nb], ah, bv[nb].z, bv[nb].w);  // h*l
#pragma unroll
                for (int nb = 0; nb < 8; nb++) mma_f16(acc[nb], al, bv[nb].x, bv[nb].y);  // l*h
            }
            BAR_ARRIVE(FREE_B(b));
#pragma unroll
            for (int i = 0; i < 8; i++) av[i] = avn[i];
        }
    }

    // ================= epilogue (64 rows) =================
    __syncthreads();
    float* sc = (float*)smu;               // [64][66] overlays the ring
    int*   counts = (int*)(smu + CNT);
    int*   i1a = (int*)(smu + I1A);
    int*   i2a = (int*)(smu + I2A);
    float* g1a = (float*)(smu + G1A);
    float* g2a = (float*)(smu + G2A);

    if (is_consumer) {
        const int r0 = wid * 16 + g;
#pragma unroll
        for (int nb = 0; nb < 8; nb++) {
            int cc = nb * 8 + t4 * 2;
            float2 v0; v0.x = acc[nb][0]; v0.y = acc[nb][1];
            float2 v1; v1.x = acc[nb][2]; v1.y = acc[nb][3];
            *(float2*)(sc + r0 * SC2 + cc)       = v0;
            *(float2*)(sc + (r0 + 8) * SC2 + cc) = v1;
        }
    }
    if (tid < EE) counts[tid] = 0;
    __syncthreads();

    // add noise (coalesced)
    for (int flat = tid; flat < BR * EE; flat += NT) {
        int r = flat >> 6, e = flat & 63;
        sc[r * SC2 + e] += noise[(size_t)row0 * EE + flat];
    }
    __syncthreads();

    // per-row top-2 + gates (renormalized top-2 softmax == sigmoid of score diff)
    if (tid < BR) {
        const int row = tid;
        const float* p = sc + row * SC2;
        float m1 = -3.402823466e38f, m2 = -3.402823466e38f;
        int b1 = 0, b2 = 0;
#pragma unroll
        for (int e = 0; e < EE; e++) {
            float z = p[e];
            if (z > m1) { m2 = m1; b2 = b1; m1 = z; b1 = e; }
            else if (z > m2) { m2 = z; b2 = e; }
        }
        float e2 = __expf(m2 - m1);
        float inv = 1.0f / (1.0f + e2);
        float g1 = inv, g2 = e2 * inv;
        i1a[row] = b1; i2a[row] = b2; g1a[row] = g1; g2a[row] = g2;
        atomicAdd(&counts[b1], 1);
        atomicAdd(&counts[b2], 1);
        if (write_extras) {
            float2 iv; iv.x = (float)b1; iv.y = (float)b2;
            *(float2*)(out + IDX_OFF + (size_t)(row0 + row) * 2) = iv;
            float2 gv; gv.x = g1; gv.y = g2;
            *(float2*)(out + GATE_OFF + (size_t)(row0 + row) * 2) = gv;
        }
    }
    __syncthreads();

    // combine tensor (float4 coalesced)
    for (int chunk = tid; chunk < BR * 16; chunk += NT) {
        int r = chunk >> 4, c4 = chunk & 15;
        int b1 = i1a[r], b2 = i2a[r];
        float G1 = g1a[r], G2 = g2a[r];
        int cc = c4 * 4;
        float4 v;
        v.x = (cc     == b1) ? G1 : ((cc     == b2) ? G2 : 0.0f);
        v.y = (cc + 1 == b1) ? G1 : ((cc + 1 == b2) ? G2 : 0.0f);
        v.z = (cc + 2 == b1) ? G1 : ((cc + 2 == b2) ? G2 : 0.0f);
        v.w = (cc + 3 == b1) ? G1 : ((cc + 3 == b2) ? G2 : 0.0f);
        *(float4*)(out + (size_t)(row0 + r) * EE + cc) = v;
    }

    if (write_extras && tid < EE) {
        int cnt = counts[tid];
        if (cnt > 0) atomicAdd(out + ACT_OFF + tid, (float)cnt);
    }
}

extern "C" void kernel_launch(void* const* d_in, const int* in_sizes, int n_in,
                              void* d_out, int out_size) {
    const float* x     = (const float*)d_in[0];
    const float* w     = (const float*)d_in[1];
    const float* noise = (const float*)d_in[2];
    float* out = (float*)d_out;

    const int write_extras = ((size_t)out_size >= FULL_OUT) ? 1 : 0;

    cudaFuncSetAttribute(router_mma_kernel,
                         cudaFuncAttributeMaxDynamicSharedMemorySize, SMEM_BYTES);

    prep_kernel<<<256, 256>>>(w, out, write_extras);
    router_mma_kernel<<<TT / BR, NT, SMEM_BYTES>>>(x, noise, out, write_extras);
}

// round 12
// speedup vs baseline: 1.2671x; 1.2671x over previous
#include <cuda_runtime.h>
#include <cuda_fp16.h>
#include <cstdint>

#define TT 16384
#define DD 2048
#define EE 64
#define BM 128
#define BK 32
#define NT 512
#define NCH 32                 // chunks per K-set (each set covers K=1024)

// ---- smem layout (u32 offsets) ----
#define A_ROW_U32 20           // 128 rows x 20 u32 (16 data + 4 pad) -> conflict-free frag reads
#define A_PLANE (BM * A_ROW_U32)              // 2560
#define SET_U32 14336
#define AOFF(s,b,pl) ((s)*SET_U32 + (b)*5120 + (pl)*A_PLANE)
#define BOFF(s,b)    ((s)*SET_U32 + 10240 + (b)*2048)
#define SMEM_U32 (2 * SET_U32)                // 28672
#define SMEM_BYTES (SMEM_U32 * 4)             // 114688

// epilogue overlay (u32 offsets)
#define SC_STRIDE 66
#define BOARD_U32 (BM * SC_STRIDE)            // 8448
#define CNT (2 * BOARD_U32)
#define I1A (CNT + 64)
#define I2A (I1A + 128)
#define G1A (I2A + 128)
#define G2A (G1A + 128)

// ---- output layout (floats) ----
#define IDX_OFF  ((size_t)TT * EE)
#define GATE_OFF (IDX_OFF + 2 * (size_t)TT)
#define ACT_OFF  (GATE_OFF + 2 * (size_t)TT)
#define FULL_OUT (ACT_OFF + EE)

// w pre-split to fp16 hi/lo, fragment-major: [k16-step 128][nb 8][lane 32] uint4
// uint4 = {b0_hi, b1_hi, b0_lo, b1_lo}
__device__ uint4 g_w_frag[128 * 8 * 32];

__device__ __forceinline__ uint32_t packh2(__half a, __half b) {
    uint32_t u;
    asm("mov.b32 %0, {%1, %2};" : "=r"(u) : "h"(__half_as_ushort(a)), "h"(__half_as_ushort(b)));
    return u;
}
__device__ __forceinline__ void split_f16(float x, __half& h, __half& l) {
    h = __float2half_rn(x);
    l = __float2half_rn(x - __half2float(h));
}
__device__ __forceinline__ void mma_f16(float* d, const uint32_t* a, uint32_t b0, uint32_t b1) {
    asm volatile(
        "mma.sync.aligned.m16n8k16.row.col.f32.f16.f16.f32 "
        "{%0,%1,%2,%3}, {%4,%5,%6,%7}, {%8,%9}, {%0,%1,%2,%3};"
        : "+f"(d[0]), "+f"(d[1]), "+f"(d[2]), "+f"(d[3])
        : "r"(a[0]), "r"(a[1]), "r"(a[2]), "r"(a[3]), "r"(b0), "r"(b1));
}
#define BARSET(s) asm volatile("bar.sync %0, %1;" :: "r"((s) + 1), "r"(256) : "memory")

// ======================= prep: w -> fragment-major fp16 hi/lo (fast) =======================
__global__ void prep_kernel(const float* __restrict__ w, float* __restrict__ out, int we) {
    int t = blockIdx.x * 256 + threadIdx.x;   // 65536 threads, one per u32 pair
    int q = t >> 1, b = t & 1;
    int ks = q >> 8, rem = q & 255, nb = rem >> 5, l = rem & 31;
    int n = nb * 8 + (l >> 2), tig = l & 3;
    int k0 = ks * 16 + 2 * tig + b * 8;
    float w0 = w[(size_t)k0 * EE + n];
    float w1 = w[(size_t)(k0 + 1) * EE + n];
    __half h0, l0, h1, l1;
    split_f16(w0, h0, l0);
    split_f16(w1, h1, l1);
    uint32_t* o32 = (uint32_t*)g_w_frag;
    o32[q * 4 + b]     = packh2(h0, h1);   // hi
    o32[q * 4 + 2 + b] = packh2(l0, l1);   // lo
    if (we && t < EE) out[ACT_OFF + t] = 0.0f;
}

// ======================= main kernel (R4 structure, 3 passes) =======================
__global__ __launch_bounds__(NT, 1)
void router_mma_kernel(const float* __restrict__ x,
                       const float* __restrict__ noise,
                       float* __restrict__ out,
                       int write_extras) {
    extern __shared__ uint32_t smu[];
    const int tid = threadIdx.x;
    const int wid = tid >> 5;
    const int lid = tid & 31;
    const int set = tid >> 8;          // K-set: 0 -> k<1024, 1 -> k>=1024
    const int st  = tid & 255;         // thread id within set
    const int ws  = wid & 7;           // warp id within set
    const int row0 = blockIdx.x * BM;

    const int wr0 = (ws >> 1) * 32;    // warp row base (32-row tile)
    const int chf = ws & 1;            // warp col half (32 cols)
    const int g   = lid >> 2;          // groupID
    const int tig = lid & 3;

    float acc[2][4][4];
#pragma unroll
    for (int mb = 0; mb < 2; mb++)
#pragma unroll
        for (int nb = 0; nb < 4; nb++)
#pragma unroll
            for (int i = 0; i < 4; i++) acc[mb][nb][i] = 0.0f;

    const size_t xko = (size_t)set * 1024;   // this set's K offset in x
    const int wfb = set * 64;                // this set's first k16-step in g_w_frag

    // ---- produce chunk 0 ----
    {
        uint32_t* Ah = smu + AOFF(set, 0, 0);
        uint32_t* Al = smu + AOFF(set, 0, 1);
#pragma unroll
        for (int j = 0; j < 4; j++) {
            int flat = st + 256 * j;               // 1024 float4 of x tile
            int r = flat >> 3, kc = flat & 7;
            float4 v = *(const float4*)(x + (size_t)(row0 + r) * DD + xko + kc * 4);
            __half hx, lx, hy, ly, hz, lz, hw, lw;
            split_f16(v.x, hx, lx); split_f16(v.y, hy, ly);
            split_f16(v.z, hz, lz); split_f16(v.w, hw, lw);
            *(uint2*)(Ah + r * A_ROW_U32 + kc * 2) = make_uint2(packh2(hx, hy), packh2(hz, hw));
            *(uint2*)(Al + r * A_ROW_U32 + kc * 2) = make_uint2(packh2(lx, ly), packh2(lz, lw));
        }
        uint4* Bs = (uint4*)(smu + BOFF(set, 0));
        const uint4* Bg = g_w_frag + (size_t)wfb * 256;
#pragma unroll
        for (int j = 0; j < 2; j++) Bs[st + 256 * j] = Bg[st + 256 * j];
    }
    BARSET(set);

    int buf = 0;
    for (int c = 0; c < NCH; ++c) {
        const bool more = (c + 1 < NCH);
        float4 xr[4];
        uint4  br[2];
        if (more) {
            const size_t kb = xko + (size_t)(c + 1) * BK;
#pragma unroll
            for (int j = 0; j < 4; j++) {
                int flat = st + 256 * j;
                int r = flat >> 3, kc = flat & 7;
                xr[j] = *(const float4*)(x + (size_t)(row0 + r) * DD + kb + kc * 4);
            }
            const uint4* Bg = g_w_frag + (size_t)(wfb + (c + 1) * 2) * 256;
#pragma unroll
            for (int j = 0; j < 2; j++) br[j] = Bg[st + 256 * j];
        }

        // ---- MMA on current buffer (3 passes: h*h, h*l, l*h) ----
        const uint32_t* Ah = smu + AOFF(set, buf, 0);
        const uint32_t* Al = smu + AOFF(set, buf, 1);
        const uint4*    Bs = (const uint4*)(smu + BOFF(set, buf));
#pragma unroll
        for (int ks = 0; ks < 2; ks++) {
            const int o = ks * 8 + tig;
            uint32_t ah[2][4], al[2][4];
#pragma unroll
            for (int mb = 0; mb < 2; mb++) {
                const int r = wr0 + mb * 16 + g;
                ah[mb][0] = Ah[r * A_ROW_U32 + o];
                ah[mb][1] = Ah[(r + 8) * A_ROW_U32 + o];
                ah[mb][2] = Ah[r * A_ROW_U32 + o + 4];
                ah[mb][3] = Ah[(r + 8) * A_ROW_U32 + o + 4];
                al[mb][0] = Al[r * A_ROW_U32 + o];
                al[mb][1] = Al[(r + 8) * A_ROW_U32 + o];
                al[mb][2] = Al[r * A_ROW_U32 + o + 4];
                al[mb][3] = Al[(r + 8) * A_ROW_U32 + o + 4];
            }
#pragma unroll
            for (int nb = 0; nb < 4; nb++) {
                uint4 bv = Bs[(ks * 8 + chf * 4 + nb) * 32 + lid];
#pragma unroll
                for (int mb = 0; mb < 2; mb++) {
                    mma_f16(acc[mb][nb], ah[mb], bv.x, bv.y);   // h*h
                    mma_f16(acc[mb][nb], ah[mb], bv.z, bv.w);   // h*l
                    mma_f16(acc[mb][nb], al[mb], bv.x, bv.y);   // l*h
                }
            }
        }
        BARSET(set);

        if (more) {
            const int nbuf = buf ^ 1;
            uint32_t* Ahn = smu + AOFF(set, nbuf, 0);
            uint32_t* Aln = smu + AOFF(set, nbuf, 1);
#pragma unroll
            for (int j = 0; j < 4; j++) {
                int flat = st + 256 * j;
                int r = flat >> 3, kc = flat & 7;
                float4 v = xr[j];
                __half hx, lx, hy, ly, hz, lz, hw, lw;
                split_f16(v.x, hx, lx); split_f16(v.y, hy, ly);
                split_f16(v.z, hz, lz); split_f16(v.w, hw, lw);
                *(uint2*)(Ahn + r * A_ROW_U32 + kc * 2) = make_uint2(packh2(hx, hy), packh2(hz, hw));
                *(uint2*)(Aln + r * A_ROW_U32 + kc * 2) = make_uint2(packh2(lx, ly), packh2(lz, lw));
            }
            uint4* Bsn = (uint4*)(smu + BOFF(set, nbuf));
#pragma unroll
            for (int j = 0; j < 2; j++) Bsn[st + 256 * j] = br[j];
            BARSET(set);
            buf = nbuf;
        }
    }

    // ================= epilogue =================
    __syncthreads();                       // both sets done; reuse smem
    float* sc0 = (float*)smu;              // board set 0: [128][66]
    float* sc1 = (float*)(smu + BOARD_U32);
    float* scb = set ? sc1 : sc0;
    int*   counts = (int*)(smu + CNT);
    int*   i1a = (int*)(smu + I1A);
    int*   i2a = (int*)(smu + I2A);
    float* g1a = (float*)(smu + G1A);
    float* g2a = (float*)(smu + G2A);

    // scatter accumulators to this set's board
#pragma unroll
    for (int mb = 0; mb < 2; mb++) {
        int rbase = wr0 + mb * 16 + g;
#pragma unroll
        for (int nb = 0; nb < 4; nb++) {
            int cc = chf * 32 + nb * 8 + tig * 2;
            float2 v0; v0.x = acc[mb][nb][0]; v0.y = acc[mb][nb][1];
            float2 v1; v1.x = acc[mb][nb][2]; v1.y = acc[mb][nb][3];
            *(float2*)(scb + rbase * SC_STRIDE + cc)       = v0;
            *(float2*)(scb + (rbase + 8) * SC_STRIDE + cc) = v1;
        }
    }
    if (tid < EE) counts[tid] = 0;
    __syncthreads();

    // sum K-halves + noise (coalesced)
#pragma unroll
    for (int j = 0; j < 16; j++) {
        int flat = tid + NT * j;           // 8192 elems
        int r = flat >> 6, e = flat & 63;
        sc0[r * SC_STRIDE + e] = sc0[r * SC_STRIDE + e] + sc1[r * SC_STRIDE + e]
                               + noise[(size_t)row0 * EE + flat];
    }
    __syncthreads();

    // per-row top-2 + gates (renormalized top-2 softmax == sigmoid of score diff)
    if (tid < BM) {
        const int row = tid;
        const float* p = sc0 + row * SC_STRIDE;
        float m1 = -3.402823466e38f, m2 = -3.402823466e38f;
        int b1 = 0, b2 = 0;
#pragma unroll
        for (int e = 0; e < EE; e++) {
            float z = p[e];
            if (z > m1) { m2 = m1; b2 = b1; m1 = z; b1 = e; }
            else if (z > m2) { m2 = z; b2 = e; }
        }
        float e2 = __expf(m2 - m1);
        float inv = 1.0f / (1.0f + e2);
        float g1 = inv, g2 = e2 * inv;
        i1a[row] = b1; i2a[row] = b2; g1a[row] = g1; g2a[row] = g2;
        atomicAdd(&counts[b1], 1);
        atomicAdd(&counts[b2], 1);
        if (write_extras) {
            float2 iv; iv.x = (float)b1; iv.y = (float)b2;
            *(float2*)(out + IDX_OFF + (size_t)(row0 + row) * 2) = iv;
            float2 gv; gv.x = g1; gv.y = g2;
            *(float2*)(out + GATE_OFF + (size_t)(row0 + row) * 2) = gv;
        }
    }
    __syncthreads();

    // combine tensor (float4 coalesced)
#pragma unroll
    for (int j = 0; j < 4; j++) {
        int chunk = tid + NT * j;          // 2048 float4
        int r = chunk >> 4, c4 = chunk & 15;
        int b1 = i1a[r], b2 = i2a[r];
        float G1 = g1a[r], G2 = g2a[r];
        int cc = c4 * 4;
        float4 v;
        v.x = (cc     == b1) ? G1 : ((cc     == b2) ? G2 : 0.0f);
        v.y = (cc + 1 == b1) ? G1 : ((cc + 1 == b2) ? G2 : 0.0f);
        v.z = (cc + 2 == b1) ? G1 : ((cc + 2 == b2) ? G2 : 0.0f);
        v.w = (cc + 3 == b1) ? G1 : ((cc + 3 == b2) ? G2 : 0.0f);
        *(float4*)(out + (size_t)(row0 + r) * EE + cc) = v;
    }

    if (write_extras && tid < EE) {
        int cnt = counts[tid];
        if (cnt > 0) atomicAdd(out + ACT_OFF + tid, (float)cnt);
    }
}

extern "C" void kernel_launch(void* const* d_in, const int* in_sizes, int n_in,
                              void* d_out, int out_size) {
    const float* x     = (const float*)d_in[0];
    const float* w     = (const float*)d_in[1];
    const float* noise = (const float*)d_in[2];
    float* out = (float*)d_out;

    const int write_extras = ((size_t)out_size >= FULL_OUT) ? 1 : 0;

    cudaFuncSetAttribute(router_mma_kernel,
                         cudaFuncAttributeMaxDynamicSharedMemorySize, SMEM_BYTES);

    prep_kernel<<<256, 256>>>(w, out, write_extras);
    router_mma_kernel<<<TT / BM, NT, SMEM_BYTES>>>(x, noise, out, write_extras);
}

// round 13
// speedup vs baseline: 1.3048x; 1.0298x over previous
#include <cuda_runtime.h>
#include <cuda_fp16.h>
#include <cstdint>

#define TT 16384
#define DD 2048
#define EE 64
#define BM 128
#define BK 32
#define NT 512
#define NCH 32                 // chunks per K-set (each set covers K=1024)

// ---- smem layout (u32 offsets) ----
#define A_ROW_U32 20           // 128 rows x 20 u32 (16 data + 4 pad) -> conflict-free frag reads
#define A_PLANE (BM * A_ROW_U32)              // 2560
#define SET_U32 14336
#define AOFF(s,b,pl) ((s)*SET_U32 + (b)*5120 + (pl)*A_PLANE)
#define BOFF(s,b)    ((s)*SET_U32 + 10240 + (b)*2048)
#define SMEM_U32 (2 * SET_U32)                // 28672
#define SMEM_BYTES (SMEM_U32 * 4)             // 114688

// epilogue overlay (u32 offsets)
#define SC_STRIDE 66
#define BOARD_U32 (BM * SC_STRIDE)            // 8448
#define CNT (2 * BOARD_U32)
#define I1A (CNT + 64)
#define I2A (I1A + 128)
#define G1A (I2A + 128)
#define G2A (G1A + 128)

// ---- output layout (floats) ----
#define IDX_OFF  ((size_t)TT * EE)
#define GATE_OFF (IDX_OFF + 2 * (size_t)TT)
#define ACT_OFF  (GATE_OFF + 2 * (size_t)TT)
#define FULL_OUT (ACT_OFF + EE)

// w pre-split to fp16 hi/lo, fragment-major: [k16-step 128][nb 8][lane 32] uint4
// uint4 = {b0_hi, b1_hi, b0_lo, b1_lo}
__device__ uint4 g_w_frag[128 * 8 * 32];

__device__ __forceinline__ uint32_t packh2(__half a, __half b) {
    uint32_t u;
    asm("mov.b32 %0, {%1, %2};" : "=r"(u) : "h"(__half_as_ushort(a)), "h"(__half_as_ushort(b)));
    return u;
}
__device__ __forceinline__ void split_f16(float x, __half& h, __half& l) {
    h = __float2half_rn(x);
    l = __float2half_rn(x - __half2float(h));
}
__device__ __forceinline__ void mma_f16(float* d, const uint32_t* a, uint32_t b0, uint32_t b1) {
    asm volatile(
        "mma.sync.aligned.m16n8k16.row.col.f32.f16.f16.f32 "
        "{%0,%1,%2,%3}, {%4,%5,%6,%7}, {%8,%9}, {%0,%1,%2,%3};"
        : "+f"(d[0]), "+f"(d[1]), "+f"(d[2]), "+f"(d[3])
        : "r"(a[0]), "r"(a[1]), "r"(a[2]), "r"(a[3]), "r"(b0), "r"(b1));
}
#define BARSET(s) asm volatile("bar.sync %0, %1;" :: "r"((s) + 1), "r"(256) : "memory")

// ======================= prep: coalesced w -> fragment-major fp16 hi/lo =======================
__global__ void prep_kernel(const float* __restrict__ w, float* __restrict__ out, int we) {
    __shared__ float ws[16 * 64];
    const int ks = blockIdx.x;             // one k16-step per block (128 blocks)
    const int t  = threadIdx.x;            // 256 threads

    // stage 16x64 slice, fully coalesced (256 float4)
    ((float4*)ws)[t] = ((const float4*)(w + (size_t)ks * 16 * EE))[t];
    __syncthreads();

    // one fragment uint4 per thread, coalesced store
    const int nb = t >> 5, l = t & 31;
    const int n = nb * 8 + (l >> 2), tig = l & 3;
    const int k0 = 2 * tig, k1 = k0 + 8;
    float w00 = ws[k0 * EE + n],       w01 = ws[(k0 + 1) * EE + n];
    float w10 = ws[k1 * EE + n],       w11 = ws[(k1 + 1) * EE + n];
    __half h00, l00, h01, l01, h10, l10, h11, l11;
    split_f16(w00, h00, l00); split_f16(w01, h01, l01);
    split_f16(w10, h10, l10); split_f16(w11, h11, l11);
    uint4 v;
    v.x = packh2(h00, h01);
    v.y = packh2(h10, h11);
    v.z = packh2(l00, l01);
    v.w = packh2(l10, l11);
    g_w_frag[ks * 256 + t] = v;
    if (we && ks == 0 && t < EE) out[ACT_OFF + t] = 0.0f;
}

// ======================= main kernel (R4 structure, 3 passes, pass-major) =======================
__global__ __launch_bounds__(NT, 1)
void router_mma_kernel(const float* __restrict__ x,
                       const float* __restrict__ noise,
                       float* __restrict__ out,
                       int write_extras) {
    extern __shared__ uint32_t smu[];
    const int tid = threadIdx.x;
    const int wid = tid >> 5;
    const int lid = tid & 31;
    const int set = tid >> 8;          // K-set: 0 -> k<1024, 1 -> k>=1024
    const int st  = tid & 255;         // thread id within set
    const int ws  = wid & 7;           // warp id within set
    const int row0 = blockIdx.x * BM;

    const int wr0 = (ws >> 1) * 32;    // warp row base (32-row tile)
    const int chf = ws & 1;            // warp col half (32 cols)
    const int g   = lid >> 2;          // groupID
    const int tig = lid & 3;

    float acc[2][4][4];
#pragma unroll
    for (int mb = 0; mb < 2; mb++)
#pragma unroll
        for (int nb = 0; nb < 4; nb++)
#pragma unroll
            for (int i = 0; i < 4; i++) acc[mb][nb][i] = 0.0f;

    const size_t xko = (size_t)set * 1024;   // this set's K offset in x
    const int wfb = set * 64;                // this set's first k16-step in g_w_frag

    // ---- produce chunk 0 ----
    {
        uint32_t* Ah = smu + AOFF(set, 0, 0);
        uint32_t* Al = smu + AOFF(set, 0, 1);
#pragma unroll
        for (int j = 0; j < 4; j++) {
            int flat = st + 256 * j;               // 1024 float4 of x tile
            int r = flat >> 3, kc = flat & 7;
            float4 v = *(const float4*)(x + (size_t)(row0 + r) * DD + xko + kc * 4);
            __half hx, lx, hy, ly, hz, lz, hw, lw;
            split_f16(v.x, hx, lx); split_f16(v.y, hy, ly);
            split_f16(v.z, hz, lz); split_f16(v.w, hw, lw);
            *(uint2*)(Ah + r * A_ROW_U32 + kc * 2) = make_uint2(packh2(hx, hy), packh2(hz, hw));
            *(uint2*)(Al + r * A_ROW_U32 + kc * 2) = make_uint2(packh2(lx, ly), packh2(lz, lw));
        }
        uint4* Bs = (uint4*)(smu + BOFF(set, 0));
        const uint4* Bg = g_w_frag + (size_t)wfb * 256;
#pragma unroll
        for (int j = 0; j < 2; j++) Bs[st + 256 * j] = Bg[st + 256 * j];
    }
    BARSET(set);

    int buf = 0;
    for (int c = 0; c < NCH; ++c) {
        const bool more = (c + 1 < NCH);
        float4 xr[4];
        uint4  br[2];
        if (more) {
            const size_t kb = xko + (size_t)(c + 1) * BK;
#pragma unroll
            for (int j = 0; j < 4; j++) {
                int flat = st + 256 * j;
                int r = flat >> 3, kc = flat & 7;
                xr[j] = *(const float4*)(x + (size_t)(row0 + r) * DD + kb + kc * 4);
            }
            const uint4* Bg = g_w_frag + (size_t)(wfb + (c + 1) * 2) * 256;
#pragma unroll
            for (int j = 0; j < 2; j++) br[j] = Bg[st + 256 * j];
        }

        // ---- MMA on current buffer: pass-major (8 independent MMAs per pass) ----
        const uint32_t* Ah = smu + AOFF(set, buf, 0);
        const uint32_t* Al = smu + AOFF(set, buf, 1);
        const uint4*    Bs = (const uint4*)(smu + BOFF(set, buf));
#pragma unroll
        for (int ks = 0; ks < 2; ks++) {
            const int o = ks * 8 + tig;
            uint32_t ah[2][4], al[2][4];
#pragma unroll
            for (int mb = 0; mb < 2; mb++) {
                const int r = wr0 + mb * 16 + g;
                ah[mb][0] = Ah[r * A_ROW_U32 + o];
                ah[mb][1] = Ah[(r + 8) * A_ROW_U32 + o];
                ah[mb][2] = Ah[r * A_ROW_U32 + o + 4];
                ah[mb][3] = Ah[(r + 8) * A_ROW_U32 + o + 4];
                al[mb][0] = Al[r * A_ROW_U32 + o];
                al[mb][1] = Al[(r + 8) * A_ROW_U32 + o];
                al[mb][2] = Al[r * A_ROW_U32 + o + 4];
                al[mb][3] = Al[(r + 8) * A_ROW_U32 + o + 4];
            }
            uint4 bv[4];
#pragma unroll
            for (int nb = 0; nb < 4; nb++) bv[nb] = Bs[(ks * 8 + chf * 4 + nb) * 32 + lid];
            // pass 1: h*h
#pragma unroll
            for (int nb = 0; nb < 4; nb++)
#pragma unroll
                for (int mb = 0; mb < 2; mb++) mma_f16(acc[mb][nb], ah[mb], bv[nb].x, bv[nb].y);
            // pass 2: h*l
#pragma unroll
            for (int nb = 0; nb < 4; nb++)
#pragma unroll
                for (int mb = 0; mb < 2; mb++) mma_f16(acc[mb][nb], ah[mb], bv[nb].z, bv[nb].w);
            // pass 3: l*h
#pragma unroll
            for (int nb = 0; nb < 4; nb++)
#pragma unroll
                for (int mb = 0; mb < 2; mb++) mma_f16(acc[mb][nb], al[mb], bv[nb].x, bv[nb].y);
        }
        BARSET(set);

        if (more) {
            const int nbuf = buf ^ 1;
            uint32_t* Ahn = smu + AOFF(set, nbuf, 0);
            uint32_t* Aln = smu + AOFF(set, nbuf, 1);
#pragma unroll
            for (int j = 0; j < 4; j++) {
                int flat = st + 256 * j;
                int r = flat >> 3, kc = flat & 7;
                float4 v = xr[j];
                __half hx, lx, hy, ly, hz, lz, hw, lw;
                split_f16(v.x, hx, lx); split_f16(v.y, hy, ly);
                split_f16(v.z, hz, lz); split_f16(v.w, hw, lw);
                *(uint2*)(Ahn + r * A_ROW_U32 + kc * 2) = make_uint2(packh2(hx, hy), packh2(hz, hw));
                *(uint2*)(Aln + r * A_ROW_U32 + kc * 2) = make_uint2(packh2(lx, ly), packh2(lz, lw));
            }
            uint4* Bsn = (uint4*)(smu + BOFF(set, nbuf));
#pragma unroll
            for (int j = 0; j < 2; j++) Bsn[st + 256 * j] = br[j];
            BARSET(set);
            buf = nbuf;
        }
    }

    // ================= epilogue =================
    __syncthreads();                       // both sets done; reuse smem
    float* sc0 = (float*)smu;              // board set 0: [128][66]
    float* sc1 = (float*)(smu + BOARD_U32);
    float* scb = set ? sc1 : sc0;
    int*   counts = (int*)(smu + CNT);
    int*   i1a = (int*)(smu + I1A);
    int*   i2a = (int*)(smu + I2A);
    float* g1a = (float*)(smu + G1A);
    float* g2a = (float*)(smu + G2A);

    // scatter accumulators to this set's board
#pragma unroll
    for (int mb = 0; mb < 2; mb++) {
        int rbase = wr0 + mb * 16 + g;
#pragma unroll
        for (int nb = 0; nb < 4; nb++) {
            int cc = chf * 32 + nb * 8 + tig * 2;
            float2 v0; v0.x = acc[mb][nb][0]; v0.y = acc[mb][nb][1];
            float2 v1; v1.x = acc[mb][nb][2]; v1.y = acc[mb][nb][3];
            *(float2*)(scb + rbase * SC_STRIDE + cc)       = v0;
            *(float2*)(scb + (rbase + 8) * SC_STRIDE + cc) = v1;
        }
    }
    if (tid < EE) counts[tid] = 0;
    __syncthreads();

    // sum K-halves + noise (coalesced)
#pragma unroll
    for (int j = 0; j < 16; j++) {
        int flat = tid + NT * j;           // 8192 elems
        int r = flat >> 6, e = flat & 63;
        sc0[r * SC_STRIDE + e] = sc0[r * SC_STRIDE + e] + sc1[r * SC_STRIDE + e]
                               + noise[(size_t)row0 * EE + flat];
    }
    __syncthreads();

    // per-row top-2 + gates (renormalized top-2 softmax == sigmoid of score diff)
    if (tid < BM) {
        const int row = tid;
        const float* p = sc0 + row * SC_STRIDE;
        float m1 = -3.402823466e38f, m2 = -3.402823466e38f;
        int b1 = 0, b2 = 0;
#pragma unroll
        for (int e = 0; e < EE; e++) {
            float z = p[e];
            if (z > m1) { m2 = m1; b2 = b1; m1 = z; b1 = e; }
            else if (z > m2) { m2 = z; b2 = e; }
        }
        float e2 = __expf(m2 - m1);
        float inv = 1.0f / (1.0f + e2);
        float g1 = inv, g2 = e2 * inv;
        i1a[row] = b1; i2a[row] = b2; g1a[row] = g1; g2a[row] = g2;
        atomicAdd(&counts[b1], 1);
        atomicAdd(&counts[b2], 1);
        if (write_extras) {
            float2 iv; iv.x = (float)b1; iv.y = (float)b2;
            *(float2*)(out + IDX_OFF + (size_t)(row0 + row) * 2) = iv;
            float2 gv; gv.x = g1; gv.y = g2;
            *(float2*)(out + GATE_OFF + (size_t)(row0 + row) * 2) = gv;
        }
    }
    __syncthreads();

    // combine tensor (float4 coalesced)
#pragma unroll
    for (int j = 0; j < 4; j++) {
        int chunk = tid + NT * j;          // 2048 float4
        int r = chunk >> 4, c4 = chunk & 15;
        int b1 = i1a[r], b2 = i2a[r];
        float G1 = g1a[r], G2 = g2a[r];
        int cc = c4 * 4;
        float4 v;
        v.x = (cc     == b1) ? G1 : ((cc     == b2) ? G2 : 0.0f);
        v.y = (cc + 1 == b1) ? G1 : ((cc + 1 == b2) ? G2 : 0.0f);
        v.z = (cc + 2 == b1) ? G1 : ((cc + 2 == b2) ? G2 : 0.0f);
        v.w = (cc + 3 == b1) ? G1 : ((cc + 3 == b2) ? G2 : 0.0f);
        *(float4*)(out + (size_t)(row0 + r) * EE + cc) = v;
    }

    if (write_extras && tid < EE) {
        int cnt = counts[tid];
        if (cnt > 0) atomicAdd(out + ACT_OFF + tid, (float)cnt);
    }
}

extern "C" void kernel_launch(void* const* d_in, const int* in_sizes, int n_in,
                              void* d_out, int out_size) {
    const float* x     = (const float*)d_in[0];
    const float* w     = (const float*)d_in[1];
    const float* noise = (const float*)d_in[2];
    float* out = (float*)d_out;

    const int write_extras = ((size_t)out_size >= FULL_OUT) ? 1 : 0;

    cudaFuncSetAttribute(router_mma_kernel,
                         cudaFuncAttributeMaxDynamicSharedMemorySize, SMEM_BYTES);

    prep_kernel<<<128, 256>>>(w, out, write_extras);
    router_mma_kernel<<<TT / BM, NT, SMEM_BYTES>>>(x, noise, out, write_extras);
}

// round 14
// speedup vs baseline: 1.3573x; 1.0402x over previous
#include <cuda_runtime.h>
#include <cuda_fp16.h>
#include <cstdint>

#define TT 16384
#define DD 2048
#define EE 64
#define BM 128
#define BK 32
#define NT 512
#define NCH 32                 // chunks per K-set (each set covers K=1024)
#define NBUF 3

// ---- smem layout (u32 offsets) ----
#define A_ROW_U32 20           // 128 rows x 20 u32 (16 data + 4 pad) -> conflict-free frag reads
#define A_PLANE (BM * A_ROW_U32)              // 2560
#define BUF_U32 (2 * A_PLANE + 2048)          // 7168
#define SET_U32 (NBUF * BUF_U32)              // 21504
#define AOFF(s,b,pl) ((s)*SET_U32 + (b)*BUF_U32 + (pl)*A_PLANE)
#define BOFF(s,b)    ((s)*SET_U32 + (b)*BUF_U32 + 2*A_PLANE)
#define SMEM_U32 (2 * SET_U32)                // 43008
#define SMEM_BYTES (SMEM_U32 * 4)             // 172032

// epilogue overlay (u32 offsets)
#define SC_STRIDE 66
#define BOARD_U32 (BM * SC_STRIDE)            // 8448
#define CNT (2 * BOARD_U32)
#define I1A (CNT + 64)
#define I2A (I1A + 128)
#define G1A (I2A + 128)
#define G2A (G1A + 128)

// ---- output layout (floats) ----
#define IDX_OFF  ((size_t)TT * EE)
#define GATE_OFF (IDX_OFF + 2 * (size_t)TT)
#define ACT_OFF  (GATE_OFF + 2 * (size_t)TT)
#define FULL_OUT (ACT_OFF + EE)

// w pre-split to fp16 hi/lo, fragment-major: [k16-step 128][nb 8][lane 32] uint4
// uint4 = {b0_hi, b1_hi, b0_lo, b1_lo}
__device__ uint4 g_w_frag[128 * 8 * 32];

__device__ __forceinline__ uint32_t packh2(__half a, __half b) {
    uint32_t u;
    asm("mov.b32 %0, {%1, %2};" : "=r"(u) : "h"(__half_as_ushort(a)), "h"(__half_as_ushort(b)));
    return u;
}
__device__ __forceinline__ void split_f16(float x, __half& h, __half& l) {
    h = __float2half_rn(x);
    l = __float2half_rn(x - __half2float(h));
}
__device__ __forceinline__ void mma_f16(float* d, const uint32_t* a, uint32_t b0, uint32_t b1) {
    asm volatile(
        "mma.sync.aligned.m16n8k16.row.col.f32.f16.f16.f32 "
        "{%0,%1,%2,%3}, {%4,%5,%6,%7}, {%8,%9}, {%0,%1,%2,%3};"
        : "+f"(d[0]), "+f"(d[1]), "+f"(d[2]), "+f"(d[3])
        : "r"(a[0]), "r"(a[1]), "r"(a[2]), "r"(a[3]), "r"(b0), "r"(b1));
}
#define BARSET(s) asm volatile("bar.sync %0, %1;" :: "r"((s) + 1), "r"(256) : "memory")

// ======================= prep: coalesced w -> fragment-major fp16 hi/lo =======================
__global__ void prep_kernel(const float* __restrict__ w, float* __restrict__ out, int we) {
    __shared__ float ws[16 * 64];
    const int ks = blockIdx.x;             // one k16-step per block (128 blocks)
    const int t  = threadIdx.x;            // 256 threads

    ((float4*)ws)[t] = ((const float4*)(w + (size_t)ks * 16 * EE))[t];
    __syncthreads();

    const int nb = t >> 5, l = t & 31;
    const int n = nb * 8 + (l >> 2), tig = l & 3;
    const int k0 = 2 * tig, k1 = k0 + 8;
    float w00 = ws[k0 * EE + n],       w01 = ws[(k0 + 1) * EE + n];
    float w10 = ws[k1 * EE + n],       w11 = ws[(k1 + 1) * EE + n];
    __half h00, l00, h01, l01, h10, l10, h11, l11;
    split_f16(w00, h00, l00); split_f16(w01, h01, l01);
    split_f16(w10, h10, l10); split_f16(w11, h11, l11);
    uint4 v;
    v.x = packh2(h00, h01);
    v.y = packh2(h10, h11);
    v.z = packh2(l00, l01);
    v.w = packh2(l10, l11);
    g_w_frag[ks * 256 + t] = v;
    if (we && ks == 0 && t < EE) out[ACT_OFF + t] = 0.0f;
}

// ======================= main kernel: 3 buffers, 1 barrier/chunk, pass-major =======================
__global__ __launch_bounds__(NT, 1)
void router_mma_kernel(const float* __restrict__ x,
                       const float* __restrict__ noise,
                       float* __restrict__ out,
                       int write_extras) {
    extern __shared__ uint32_t smu[];
    const int tid = threadIdx.x;
    const int wid = tid >> 5;
    const int lid = tid & 31;
    const int set = tid >> 8;          // K-set: 0 -> k<1024, 1 -> k>=1024
    const int st  = tid & 255;         // thread id within set
    const int ws  = wid & 7;           // warp id within set
    const int row0 = blockIdx.x * BM;

    const int wr0 = (ws >> 1) * 32;    // warp row base (32-row tile)
    const int chf = ws & 1;            // warp col half (32 cols)
    const int g   = lid >> 2;          // groupID
    const int tig = lid & 3;

    float acc[2][4][4];
#pragma unroll
    for (int mb = 0; mb < 2; mb++)
#pragma unroll
        for (int nb = 0; nb < 4; nb++)
#pragma unroll
            for (int i = 0; i < 4; i++) acc[mb][nb][i] = 0.0f;

    const size_t xko = (size_t)set * 1024;   // this set's K offset in x
    const int wfb = set * 64;                // this set's first k16-step in g_w_frag

    // ---- produce chunk 0 into buf 0 ----
    {
        uint32_t* Ah = smu + AOFF(set, 0, 0);
        uint32_t* Al = smu + AOFF(set, 0, 1);
#pragma unroll
        for (int j = 0; j < 4; j++) {
            int flat = st + 256 * j;               // 1024 float4 of x tile
            int r = flat >> 3, kc = flat & 7;
            float4 v = *(const float4*)(x + (size_t)(row0 + r) * DD + xko + kc * 4);
            __half hx, lx, hy, ly, hz, lz, hw, lw;
            split_f16(v.x, hx, lx); split_f16(v.y, hy, ly);
            split_f16(v.z, hz, lz); split_f16(v.w, hw, lw);
            *(uint2*)(Ah + r * A_ROW_U32 + kc * 2) = make_uint2(packh2(hx, hy), packh2(hz, hw));
            *(uint2*)(Al + r * A_ROW_U32 + kc * 2) = make_uint2(packh2(lx, ly), packh2(lz, lw));
        }
        uint4* Bs = (uint4*)(smu + BOFF(set, 0));
        const uint4* Bg = g_w_frag + (size_t)wfb * 256;
#pragma unroll
        for (int j = 0; j < 2; j++) Bs[st + 256 * j] = Bg[st + 256 * j];
    }
    BARSET(set);

    int buf = 0;
    for (int c = 0; c < NCH; ++c) {
        const bool more = (c + 1 < NCH);
        const int nbuf = (buf + 1 == NBUF) ? 0 : buf + 1;
        float4 xr[4];
        uint4  br[2];
        if (more) {
            const size_t kb = xko + (size_t)(c + 1) * BK;
#pragma unroll
            for (int j = 0; j < 4; j++) {
                int flat = st + 256 * j;
                int r = flat >> 3, kc = flat & 7;
                xr[j] = *(const float4*)(x + (size_t)(row0 + r) * DD + kb + kc * 4);
            }
            const uint4* Bg = g_w_frag + (size_t)(wfb + (c + 1) * 2) * 256;
#pragma unroll
            for (int j = 0; j < 2; j++) br[j] = Bg[st + 256 * j];
        }

        // ---- MMA on current buffer: pass-major (8 independent MMAs per pass) ----
        const uint32_t* Ah = smu + AOFF(set, buf, 0);
        const uint32_t* Al = smu + AOFF(set, buf, 1);
        const uint4*    Bs = (const uint4*)(smu + BOFF(set, buf));
#pragma unroll
        for (int ks = 0; ks < 2; ks++) {
            const int o = ks * 8 + tig;
            uint32_t ah[2][4], al[2][4];
#pragma unroll
            for (int mb = 0; mb < 2; mb++) {
                const int r = wr0 + mb * 16 + g;
                ah[mb][0] = Ah[r * A_ROW_U32 + o];
                ah[mb][1] = Ah[(r + 8) * A_ROW_U32 + o];
                ah[mb][2] = Ah[r * A_ROW_U32 + o + 4];
                ah[mb][3] = Ah[(r + 8) * A_ROW_U32 + o + 4];
                al[mb][0] = Al[r * A_ROW_U32 + o];
                al[mb][1] = Al[(r + 8) * A_ROW_U32 + o];
                al[mb][2] = Al[r * A_ROW_U32 + o + 4];
                al[mb][3] = Al[(r + 8) * A_ROW_U32 + o + 4];
            }
            uint4 bv[4];
#pragma unroll
            for (int nb = 0; nb < 4; nb++) bv[nb] = Bs[(ks * 8 + chf * 4 + nb) * 32 + lid];
            // pass 1: h*h
#pragma unroll
            for (int nb = 0; nb < 4; nb++)
#pragma unroll
                for (int mb = 0; mb < 2; mb++) mma_f16(acc[mb][nb], ah[mb], bv[nb].x, bv[nb].y);
            // pass 2: h*l
#pragma unroll
            for (int nb = 0; nb < 4; nb++)
#pragma unroll
                for (int mb = 0; mb < 2; mb++) mma_f16(acc[mb][nb], ah[mb], bv[nb].z, bv[nb].w);
            // pass 3: l*h
#pragma unroll
            for (int nb = 0; nb < 4; nb++)
#pragma unroll
                for (int mb = 0; mb < 2; mb++) mma_f16(acc[mb][nb], al[mb], bv[nb].x, bv[nb].y);
        }

        // ---- store chunk c+1 into buf nbuf (safe: last read 2 bars ago) ----
        if (more) {
            uint32_t* Ahn = smu + AOFF(set, nbuf, 0);
            uint32_t* Aln = smu + AOFF(set, nbuf, 1);
#pragma unroll
            for (int j = 0; j < 4; j++) {
                int flat = st + 256 * j;
                int r = flat >> 3, kc = flat & 7;
                float4 v = xr[j];
                __half hx, lx, hy, ly, hz, lz, hw, lw;
                split_f16(v.x, hx, lx); split_f16(v.y, hy, ly);
                split_f16(v.z, hz, lz); split_f16(v.w, hw, lw);
                *(uint2*)(Ahn + r * A_ROW_U32 + kc * 2) = make_uint2(packh2(hx, hy), packh2(hz, hw));
                *(uint2*)(Aln + r * A_ROW_U32 + kc * 2) = make_uint2(packh2(lx, ly), packh2(lz, lw));
            }
            uint4* Bsn = (uint4*)(smu + BOFF(set, nbuf));
#pragma unroll
            for (int j = 0; j < 2; j++) Bsn[st + 256 * j] = br[j];
        }
        BARSET(set);
        buf = nbuf;
    }

    // ================= epilogue =================
    __syncthreads();                       // both sets done; reuse smem
    float* sc0 = (float*)smu;              // board set 0: [128][66]
    float* sc1 = (float*)(smu + BOARD_U32);
    float* scb = set ? sc1 : sc0;
    int*   counts = (int*)(smu + CNT);
    int*   i1a = (int*)(smu + I1A);
    int*   i2a = (int*)(smu + I2A);
    float* g1a = (float*)(smu + G1A);
    float* g2a = (float*)(smu + G2A);

    // scatter accumulators to this set's board
#pragma unroll
    for (int mb = 0; mb < 2; mb++) {
        int rbase = wr0 + mb * 16 + g;
#pragma unroll
        for (int nb = 0; nb < 4; nb++) {
            int cc = chf * 32 + nb * 8 + tig * 2;
            float2 v0; v0.x = acc[mb][nb][0]; v0.y = acc[mb][nb][1];
            float2 v1; v1.x = acc[mb][nb][2]; v1.y = acc[mb][nb][3];
            *(float2*)(scb + rbase * SC_STRIDE + cc)       = v0;
            *(float2*)(scb + (rbase + 8) * SC_STRIDE + cc) = v1;
        }
    }
    if (tid < EE) counts[tid] = 0;
    __syncthreads();

    // sum K-halves + noise (coalesced)
#pragma unroll
    for (int j = 0; j < 16; j++) {
        int flat = tid + NT * j;           // 8192 elems
        int r = flat >> 6, e = flat & 63;
        sc0[r * SC_STRIDE + e] = sc0[r * SC_STRIDE + e] + sc1[r * SC_STRIDE + e]
                               + noise[(size_t)row0 * EE + flat];
    }
    __syncthreads();

    // per-row top-2 + gates (renormalized top-2 softmax == sigmoid of score diff)
    if (tid < BM) {
        const int row = tid;
        const float* p = sc0 + row * SC_STRIDE;
        float m1 = -3.402823466e38f, m2 = -3.402823466e38f;
        int b1 = 0, b2 = 0;
#pragma unroll
        for (int e = 0; e < EE; e++) {
            float z = p[e];
            if (z > m1) { m2 = m1; b2 = b1; m1 = z; b1 = e; }
            else if (z > m2) { m2 = z; b2 = e; }
        }
        float e2 = __expf(m2 - m1);
        float inv = 1.0f / (1.0f + e2);
        float g1 = inv, g2 = e2 * inv;
        i1a[row] = b1; i2a[row] = b2; g1a[row] = g1; g2a[row] = g2;
        atomicAdd(&counts[b1], 1);
        atomicAdd(&counts[b2], 1);
        if (write_extras) {
            float2 iv; iv.x = (float)b1; iv.y = (float)b2;
            *(float2*)(out + IDX_OFF + (size_t)(row0 + row) * 2) = iv;
            float2 gv; gv.x = g1; gv.y = g2;
            *(float2*)(out + GATE_OFF + (size_t)(row0 + row) * 2) = gv;
        }
    }
    __syncthreads();

    // combine tensor (float4 coalesced)
#pragma unroll
    for (int j = 0; j < 4; j++) {
        int chunk = tid + NT * j;          // 2048 float4
        int r = chunk >> 4, c4 = chunk & 15;
        int b1 = i1a[r], b2 = i2a[r];
        float G1 = g1a[r], G2 = g2a[r];
        int cc = c4 * 4;
        float4 v;
        v.x = (cc     == b1) ? G1 : ((cc     == b2) ? G2 : 0.0f);
        v.y = (cc + 1 == b1) ? G1 : ((cc + 1 == b2) ? G2 : 0.0f);
        v.z = (cc + 2 == b1) ? G1 : ((cc + 2 == b2) ? G2 : 0.0f);
        v.w = (cc + 3 == b1) ? G1 : ((cc + 3 == b2) ? G2 : 0.0f);
        *(float4*)(out + (size_t)(row0 + r) * EE + cc) = v;
    }

    if (write_extras && tid < EE) {
        int cnt = counts[tid];
        if (cnt > 0) atomicAdd(out + ACT_OFF + tid, (float)cnt);
    }
}

extern "C" void kernel_launch(void* const* d_in, const int* in_sizes, int n_in,
                              void* d_out, int out_size) {
    const float* x     = (const float*)d_in[0];
    const float* w     = (const float*)d_in[1];
    const float* noise = (const float*)d_in[2];
    float* out = (float*)d_out;

    const int write_extras = ((size_t)out_size >= FULL_OUT) ? 1 : 0;

    cudaFuncSetAttribute(router_mma_kernel,
                         cudaFuncAttributeMaxDynamicSharedMemorySize, SMEM_BYTES);

    prep_kernel<<<128, 256>>>(w, out, write_extras);
    router_mma_kernel<<<TT / BM, NT, SMEM_BYTES>>>(x, noise, out, write_extras);
}